// round 14
// baseline (speedup 1.0000x reference)
#include <cuda_runtime.h>
#include <cuda_fp16.h>
#include <cstdint>

// scratch
__device__ float    g_p2[8 * 128 * 4096];
__device__ float    g_Gpart[16 * 8 * 128 * 128];
__device__ float    g_sim[8 * 128 * 128];
__device__ unsigned g_M2[8 * 8192];        // M=sim^T fp16, A-fragment-ordered
__device__ unsigned g_x16[33554432];       // X fp16 k-pair packed, B-fragment order (128MB)

// ---- k0: pre-convert X to fp16 B-fragment-ordered words ----
// word(b, kh, n) -> g_x16[b<<22 | ((nt*16 + cq4)*32 + lane)*4 + cq]
//   kh = 8*ks + 4*h + lm, cq4 = ks*2+h, lane = l4*4+lm, n = nt*32 + cq*8 + l4
//   value = f16x2{ lo = x[2kh][n], hi = x[2kh+1][n] }
__global__ __launch_bounds__(256) void k0_cvt(const float* __restrict__ x)
{
    int b = blockIdx.x >> 7;
    int ntg = (blockIdx.x & 127) * 16;
    int w = threadIdx.x >> 5, lane = threadIdx.x & 31;
    int lm = lane & 3, l4 = lane >> 2;
    const float* xb = x + ((size_t)b << 23);
    unsigned* xo = g_x16 + ((size_t)b << 22);
    for (int u = 0; u < 32; u++) {
        int idx = w * 32 + u;                 // 0..255
        int nt  = ntg + (idx >> 4);
        int cq4 = idx & 15;
        int kh  = 8 * (cq4 >> 1) + 4 * (cq4 & 1) + lm;
        const float* r0 = xb + (size_t)(2 * kh) * 65536 + nt * 32 + l4;
        const float* r1 = r0 + 65536;
        uint4 q;
        unsigned qq[4];
#pragma unroll
        for (int c = 0; c < 4; c++) {
            float f0 = __ldg(r0 + 8 * c), f1 = __ldg(r1 + 8 * c);
            asm("cvt.rn.f16x2.f32 %0, %1, %2;" : "=r"(qq[c]) : "f"(f1), "f"(f0));
        }
        q.x = qq[0]; q.y = qq[1]; q.z = qq[2]; q.w = qq[3];
        *(uint4*)(xo + (size_t)((nt * 16 + cq4) * 32 + lane) * 4) = q;
    }
}

// ---- k1: fused (dwconv3x3 s2 -> BN -> PReLU) x2 ----
#define XS_H 131
#define XS_W 132
#define P1_W 66

__global__ __launch_bounds__(256) void k1_pool(
    const float* __restrict__ x,
    const float* __restrict__ w1, const float* __restrict__ g1, const float* __restrict__ b1,
    const float* __restrict__ m1, const float* __restrict__ v1, const float* __restrict__ a1_,
    const float* __restrict__ w2, const float* __restrict__ g2, const float* __restrict__ b2,
    const float* __restrict__ m2, const float* __restrict__ v2, const float* __restrict__ a2_)
{
    extern __shared__ float sm1[];
    float* xs  = sm1;
    float* p1s = sm1 + XS_H * XS_W;

    int bc = blockIdx.x, c = bc & 127, tid = threadIdx.x;
    int oy = (blockIdx.y >> 1) * 32, ox = (blockIdx.y & 1) * 32;

    float w1r[9], w2r[9];
#pragma unroll
    for (int i = 0; i < 9; i++) { w1r[i] = w1[c * 9 + i]; w2r[i] = w2[c * 9 + i]; }
    float s1 = g1[c] * rsqrtf(v1[c] + 1e-5f), t1 = b1[c] - m1[c] * s1, al1 = a1_[c];
    float s2 = g2[c] * rsqrtf(v2[c] + 1e-5f), t2 = b2[c] - m2[c] * s2, al2 = a2_[c];

    const float* xc = x + (size_t)bc * 65536;
    int gr0 = 4 * oy - 3, gc0 = 4 * ox - 3;
    for (int idx = tid; idx < XS_H * 131; idx += 256) {
        int r = idx / 131, cc = idx % 131;
        int gr = gr0 + r, gc = gc0 + cc;
        float v = 0.f;
        if ((unsigned)gr < 256u && (unsigned)gc < 256u) v = xc[gr * 256 + gc];
        xs[r * XS_W + cc] = v;
    }
    __syncthreads();

    for (int idx = tid; idx < 65 * 65; idx += 256) {
        int j = idx / 65, i = idx % 65;
        int r1 = 2 * oy - 1 + j, c1 = 2 * ox - 1 + i;
        float v = 0.f;
        if ((unsigned)r1 < 128u && (unsigned)c1 < 128u) {
            const float* xr = xs + (2 * j) * XS_W + 2 * i;
            float acc = 0.f;
#pragma unroll
            for (int dy = 0; dy < 3; dy++)
#pragma unroll
                for (int dx = 0; dx < 3; dx++)
                    acc += w1r[dy * 3 + dx] * xr[dy * XS_W + dx];
            v = acc * s1 + t1;
            v = v > 0.f ? v : al1 * v;
        }
        p1s[j * P1_W + i] = v;
    }
    __syncthreads();

    float* outp = g_p2 + (size_t)bc * 4096;
    for (int idx = tid; idx < 32 * 32; idx += 256) {
        int j = idx >> 5, i = idx & 31;
        const float* pr = p1s + (2 * j) * P1_W + 2 * i;
        float acc = 0.f;
#pragma unroll
        for (int dy = 0; dy < 3; dy++)
#pragma unroll
            for (int dx = 0; dx < 3; dx++)
                acc += w2r[dy * 3 + dx] * pr[dy * P1_W + dx];
        float v = acc * s2 + t2;
        v = v > 0.f ? v : al2 * v;
        outp[(oy + j) * 64 + (ox + i)] = v;
    }
}

// ---- k2: Gram partials ----
#define PS_STRIDE 136
__global__ __launch_bounds__(256) void k2_gram()
{
    extern __shared__ float ps[];
    int b = blockIdx.x & 7, ch = blockIdx.x >> 3, n0 = ch * 256, tid = threadIdx.x;
    const float* pb = g_p2 + (size_t)b * 128 * 4096;

    for (int v = tid; v < 128 * 64; v += 256) {
        int c = v >> 6, q = (v & 63) << 2;
        float4 f = *(const float4*)(pb + c * 4096 + n0 + q);
        ps[(q + 0) * PS_STRIDE + c] = f.x;
        ps[(q + 1) * PS_STRIDE + c] = f.y;
        ps[(q + 2) * PS_STRIDE + c] = f.z;
        ps[(q + 3) * PS_STRIDE + c] = f.w;
    }
    __syncthreads();

    int cb = (tid >> 4) * 8, kb = (tid & 15) * 8;
    float acc[8][8];
#pragma unroll
    for (int i = 0; i < 8; i++)
#pragma unroll
        for (int j = 0; j < 8; j++) acc[i][j] = 0.f;

    for (int n = 0; n < 256; n++) {
        const float* row = ps + n * PS_STRIDE;
        float4 A0 = *(const float4*)(row + cb), A1 = *(const float4*)(row + cb + 4);
        float4 B0 = *(const float4*)(row + kb), B1 = *(const float4*)(row + kb + 4);
        float a[8]  = {A0.x, A0.y, A0.z, A0.w, A1.x, A1.y, A1.z, A1.w};
        float bb[8] = {B0.x, B0.y, B0.z, B0.w, B1.x, B1.y, B1.z, B1.w};
#pragma unroll
        for (int i = 0; i < 8; i++)
#pragma unroll
            for (int j = 0; j < 8; j++) acc[i][j] += a[i] * bb[j];
    }
    float* gp = g_Gpart + ((size_t)(ch * 8 + b) * 128) * 128;
#pragma unroll
    for (int i = 0; i < 8; i++) {
        float4 o0 = {acc[i][0], acc[i][1], acc[i][2], acc[i][3]};
        float4 o1 = {acc[i][4], acc[i][5], acc[i][6], acc[i][7]};
        *(float4*)(gp + (cb + i) * 128 + kb)     = o0;
        *(float4*)(gp + (cb + i) * 128 + kb + 4) = o1;
    }
}

// ---- k3: reduce + softmax ----
__global__ __launch_bounds__(256) void k3_softmax()
{
    int b = blockIdx.x, c = blockIdx.y * 8 + (threadIdx.x >> 5), lane = threadIdx.x & 31;
    float4 acc = make_float4(0.f, 0.f, 0.f, 0.f);
    for (int ch = 0; ch < 16; ch++) {
        float4 g = *(const float4*)(g_Gpart + ((size_t)(ch * 8 + b) * 128 + c) * 128 + lane * 4);
        acc.x += g.x; acc.y += g.y; acc.z += g.z; acc.w += g.w;
    }
    const float s = 0.015625f;
    float lx = acc.x * s, ly = acc.y * s, lz = acc.z * s, lw = acc.w * s;
    float mx = fmaxf(fmaxf(lx, ly), fmaxf(lz, lw));
#pragma unroll
    for (int o = 16; o; o >>= 1) mx = fmaxf(mx, __shfl_xor_sync(0xffffffffu, mx, o));
    float ex = expf(lx - mx), ey = expf(ly - mx), ez = expf(lz - mx), ew = expf(lw - mx);
    float sum = ex + ey + ez + ew;
#pragma unroll
    for (int o = 16; o; o >>= 1) sum += __shfl_xor_sync(0xffffffffu, sum, o);
    float inv = 1.0f / sum;
    float4 o4 = make_float4(ex * inv, ey * inv, ez * inv, ew * inv);
    *(float4*)(g_sim + ((size_t)b * 128 + c) * 128 + lane * 4) = o4;
}

// ---- k3b: pack M into A-fragment-ordered fp16 words ----
__global__ __launch_bounds__(256) void k3b_pack()
{
    int b = blockIdx.x, i0 = blockIdx.y * 2048;
    for (int idx = i0 + threadIdx.x; idx < i0 + 2048; idx += 256) {
        int word = idx & 3, lane = (idx >> 2) & 31, cg = (idx >> 7) & 7, ks = idx >> 10;
        int lm = lane & 3, l4 = lane >> 2;
        int kh = ks * 8 + lm + ((word & 2) ? 4 : 0);
        int m  = cg * 16 + l4 + ((word & 1) ? 8 : 0);
        float s0 = g_sim[((size_t)b * 128 + 2 * kh)     * 128 + m];
        float s1 = g_sim[((size_t)b * 128 + 2 * kh + 1) * 128 + m];
        unsigned wv;
        asm("cvt.rn.f16x2.f32 %0, %1, %2;" : "=r"(wv) : "f"(s1), "f"(s0));
        g_M2[b * 8192 + idx] = wv;
    }
}

// ---- k4: out[b] = M @ X, register-direct fragments, no smem/syncs ----
// grid = 8 b x 128 slices; 128 thr = 4 warps (one per 32-row m-group).
// Per warp: A (64 regs, loop-invariant) ; per 32-col tile: 16 LDG.128 B,
// 64 HMMA, 16 STG.64. 4 warps share B lines via L1.
#define MMA_F16(d, a, bfr)                                             \
    asm volatile(                                                      \
        "mma.sync.aligned.m16n8k16.row.col.f32.f16.f16.f32 "           \
        "{%0,%1,%2,%3}, {%4,%5,%6,%7}, {%8,%9}, {%0,%1,%2,%3};"        \
        : "+f"(d[0]), "+f"(d[1]), "+f"(d[2]), "+f"(d[3])               \
        : "r"(a[0]), "r"(a[1]), "r"(a[2]), "r"(a[3]),                  \
          "r"(bfr[0]), "r"(bfr[1]))

__global__ __launch_bounds__(128) void k4_gemm(float* __restrict__ out)
{
    int b  = blockIdx.x >> 7;
    int sl = blockIdx.x & 127;
    int w = threadIdx.x >> 5, lane = threadIdx.x & 31;
    int lm = lane & 3, l4 = lane >> 2;

    unsigned A[8][2][4];
    const uint4* Mg = (const uint4*)(g_M2 + b * 8192);
#pragma unroll
    for (int ks = 0; ks < 8; ks++)
#pragma unroll
        for (int mi = 0; mi < 2; mi++) {
            uint4 v = __ldg(&Mg[(ks * 8 + (w * 2 + mi)) * 32 + lane]);
            A[ks][mi][0] = v.x; A[ks][mi][1] = v.y;
            A[ks][mi][2] = v.z; A[ks][mi][3] = v.w;
        }

    const uint4* xq = (const uint4*)(g_x16 + ((size_t)b << 22));
    float* ob = out + ((size_t)b * 128 + w * 32) * 65536;

    for (int i = 0; i < 16; i++) {
        int nt = sl * 16 + i;
        uint4 Bq[16];
#pragma unroll
        for (int cq = 0; cq < 16; cq++)
            Bq[cq] = __ldg(&xq[(size_t)(nt * 16 + cq) * 32 + lane]);

        float acc[2][4][4];
#pragma unroll
        for (int mi = 0; mi < 2; mi++)
#pragma unroll
            for (int ni = 0; ni < 4; ni++)
#pragma unroll
                for (int e = 0; e < 4; e++) acc[mi][ni][e] = 0.f;

#pragma unroll
        for (int ks = 0; ks < 8; ks++) {
            unsigned b0[4] = {Bq[ks*2].x, Bq[ks*2].y, Bq[ks*2].z, Bq[ks*2].w};
            unsigned b1[4] = {Bq[ks*2+1].x, Bq[ks*2+1].y, Bq[ks*2+1].z, Bq[ks*2+1].w};
#pragma unroll
            for (int ni = 0; ni < 4; ni++) {
                unsigned bfr[2] = {b0[ni], b1[ni]};
                MMA_F16(acc[0][ni], A[ks][0], bfr);
                MMA_F16(acc[1][ni], A[ks][1], bfr);
            }
        }

#pragma unroll
        for (int mi = 0; mi < 2; mi++) {
            float* rp = ob + (size_t)(mi * 16 + l4) * 65536 + nt * 32 + 2 * lm;
#pragma unroll
            for (int ni = 0; ni < 4; ni++) {
                float2 v0 = {acc[mi][ni][0], acc[mi][ni][1]};
                float2 v1 = {acc[mi][ni][2], acc[mi][ni][3]};
                *(float2*)(rp + ni * 8)               = v0;
                *(float2*)(rp + 8 * 65536 + ni * 8)   = v1;
            }
        }
    }
}

// ---------------------------------------------------------------------------
extern "C" void kernel_launch(void* const* d_in, const int* in_sizes, int n_in,
                              void* d_out, int out_size)
{
    const float* x  = (const float*)d_in[0];
    const float* w1 = (const float*)d_in[1];
    const float* g1 = (const float*)d_in[2];
    const float* b1 = (const float*)d_in[3];
    const float* m1 = (const float*)d_in[4];
    const float* v1 = (const float*)d_in[5];
    const float* a1 = (const float*)d_in[6];
    const float* w2 = (const float*)d_in[7];
    const float* g2 = (const float*)d_in[8];
    const float* b2 = (const float*)d_in[9];
    const float* m2 = (const float*)d_in[10];
    const float* v2 = (const float*)d_in[11];
    const float* a2 = (const float*)d_in[12];
    float* out = (float*)d_out;

    const int SM1 = (XS_H * XS_W + 65 * P1_W) * 4;
    const int SM2 = 256 * PS_STRIDE * 4;
    static bool attr_done = false;
    if (!attr_done) {
        cudaFuncSetAttribute(k1_pool, cudaFuncAttributeMaxDynamicSharedMemorySize, SM1);
        cudaFuncSetAttribute(k2_gram, cudaFuncAttributeMaxDynamicSharedMemorySize, SM2);
        attr_done = true;
    }

    k0_cvt<<<1024, 256>>>(x);
    k1_pool<<<dim3(1024, 4), 256, SM1>>>(x, w1, g1, b1, m1, v1, a1,
                                         w2, g2, b2, m2, v2, a2);
    k2_gram<<<128, 256, SM2>>>();
    k3_softmax<<<dim3(8, 16), 256>>>();
    k3b_pack<<<dim3(8, 4), 256>>>();
    k4_gemm<<<1024, 128>>>(out);
}

// round 15
// speedup vs baseline: 1.3741x; 1.3741x over previous
#include <cuda_runtime.h>
#include <cuda_fp16.h>
#include <cstdint>

// scratch
__device__ float g_p2[8 * 128 * 4096];
__device__ float g_Gpart[32 * 8 * 128 * 128];   // 32 n-chunk partials
__device__ float g_sim[8 * 128 * 128];

// ---- k1: fused (dwconv3x3 s2 -> BN -> PReLU) x2 ---- (512 thr)
#define XS_H 131
#define XS_W 132
#define P1_W 66
#define K1T 512

__global__ __launch_bounds__(K1T) void k1_pool(
    const float* __restrict__ x,
    const float* __restrict__ w1, const float* __restrict__ g1, const float* __restrict__ b1,
    const float* __restrict__ m1, const float* __restrict__ v1, const float* __restrict__ a1_,
    const float* __restrict__ w2, const float* __restrict__ g2, const float* __restrict__ b2,
    const float* __restrict__ m2, const float* __restrict__ v2, const float* __restrict__ a2_)
{
    extern __shared__ float sm1[];
    float* xs  = sm1;
    float* p1s = sm1 + XS_H * XS_W;

    int bc = blockIdx.x, c = bc & 127, tid = threadIdx.x;
    int oy = (blockIdx.y >> 1) * 32, ox = (blockIdx.y & 1) * 32;

    float w1r[9], w2r[9];
#pragma unroll
    for (int i = 0; i < 9; i++) { w1r[i] = w1[c * 9 + i]; w2r[i] = w2[c * 9 + i]; }
    float s1 = g1[c] * rsqrtf(v1[c] + 1e-5f), t1 = b1[c] - m1[c] * s1, al1 = a1_[c];
    float s2 = g2[c] * rsqrtf(v2[c] + 1e-5f), t2 = b2[c] - m2[c] * s2, al2 = a2_[c];

    const float* xc = x + (size_t)bc * 65536;
    int gr0 = 4 * oy - 3, gc0 = 4 * ox - 3;
    for (int idx = tid; idx < XS_H * 131; idx += K1T) {
        int r = idx / 131, cc = idx % 131;
        int gr = gr0 + r, gc = gc0 + cc;
        float v = 0.f;
        if ((unsigned)gr < 256u && (unsigned)gc < 256u) v = xc[gr * 256 + gc];
        xs[r * XS_W + cc] = v;
    }
    __syncthreads();

    for (int idx = tid; idx < 65 * 65; idx += K1T) {
        int j = idx / 65, i = idx % 65;
        int r1 = 2 * oy - 1 + j, c1 = 2 * ox - 1 + i;
        float v = 0.f;
        if ((unsigned)r1 < 128u && (unsigned)c1 < 128u) {
            const float* xr = xs + (2 * j) * XS_W + 2 * i;
            float acc = 0.f;
#pragma unroll
            for (int dy = 0; dy < 3; dy++)
#pragma unroll
                for (int dx = 0; dx < 3; dx++)
                    acc += w1r[dy * 3 + dx] * xr[dy * XS_W + dx];
            v = acc * s1 + t1;
            v = v > 0.f ? v : al1 * v;
        }
        p1s[j * P1_W + i] = v;
    }
    __syncthreads();

    float* outp = g_p2 + (size_t)bc * 4096;
    for (int idx = tid; idx < 32 * 32; idx += K1T) {
        int j = idx >> 5, i = idx & 31;
        const float* pr = p1s + (2 * j) * P1_W + 2 * i;
        float acc = 0.f;
#pragma unroll
        for (int dy = 0; dy < 3; dy++)
#pragma unroll
            for (int dx = 0; dx < 3; dx++)
                acc += w2r[dy * 3 + dx] * pr[dy * P1_W + dx];
        float v = acc * s2 + t2;
        v = v > 0.f ? v : al2 * v;
        outp[(oy + j) * 64 + (ox + i)] = v;
    }
}

// ---- k2: Gram partials, 32 chunks of 128 n (grid 256) ----
#define PS_STRIDE 136
__global__ __launch_bounds__(256) void k2_gram()
{
    extern __shared__ float ps[];   // [128][136]
    int b = blockIdx.x & 7, ch = blockIdx.x >> 3, n0 = ch * 128, tid = threadIdx.x;
    const float* pb = g_p2 + (size_t)b * 128 * 4096;

    for (int v = tid; v < 128 * 32; v += 256) {
        int c = v >> 5, q = (v & 31) << 2;
        float4 f = *(const float4*)(pb + c * 4096 + n0 + q);
        ps[(q + 0) * PS_STRIDE + c] = f.x;
        ps[(q + 1) * PS_STRIDE + c] = f.y;
        ps[(q + 2) * PS_STRIDE + c] = f.z;
        ps[(q + 3) * PS_STRIDE + c] = f.w;
    }
    __syncthreads();

    int cb = (tid >> 4) * 8, kb = (tid & 15) * 8;
    float acc[8][8];
#pragma unroll
    for (int i = 0; i < 8; i++)
#pragma unroll
        for (int j = 0; j < 8; j++) acc[i][j] = 0.f;

    for (int n = 0; n < 128; n++) {
        const float* row = ps + n * PS_STRIDE;
        float4 A0 = *(const float4*)(row + cb), A1 = *(const float4*)(row + cb + 4);
        float4 B0 = *(const float4*)(row + kb), B1 = *(const float4*)(row + kb + 4);
        float a[8]  = {A0.x, A0.y, A0.z, A0.w, A1.x, A1.y, A1.z, A1.w};
        float bb[8] = {B0.x, B0.y, B0.z, B0.w, B1.x, B1.y, B1.z, B1.w};
#pragma unroll
        for (int i = 0; i < 8; i++)
#pragma unroll
            for (int j = 0; j < 8; j++) acc[i][j] += a[i] * bb[j];
    }
    float* gp = g_Gpart + ((size_t)(ch * 8 + b) * 128) * 128;
#pragma unroll
    for (int i = 0; i < 8; i++) {
        float4 o0 = {acc[i][0], acc[i][1], acc[i][2], acc[i][3]};
        float4 o1 = {acc[i][4], acc[i][5], acc[i][6], acc[i][7]};
        *(float4*)(gp + (cb + i) * 128 + kb)     = o0;
        *(float4*)(gp + (cb + i) * 128 + kb + 4) = o1;
    }
}

// ---- k3: reduce 32 partials + row softmax ----
__global__ __launch_bounds__(256) void k3_softmax()
{
    int b = blockIdx.x, c = blockIdx.y * 8 + (threadIdx.x >> 5), lane = threadIdx.x & 31;
    float4 acc = make_float4(0.f, 0.f, 0.f, 0.f);
    for (int ch = 0; ch < 32; ch++) {
        float4 g = *(const float4*)(g_Gpart + ((size_t)(ch * 8 + b) * 128 + c) * 128 + lane * 4);
        acc.x += g.x; acc.y += g.y; acc.z += g.z; acc.w += g.w;
    }
    const float s = 0.015625f;
    float lx = acc.x * s, ly = acc.y * s, lz = acc.z * s, lw = acc.w * s;
    float mx = fmaxf(fmaxf(lx, ly), fmaxf(lz, lw));
#pragma unroll
    for (int o = 16; o; o >>= 1) mx = fmaxf(mx, __shfl_xor_sync(0xffffffffu, mx, o));
    float ex = expf(lx - mx), ey = expf(ly - mx), ez = expf(lz - mx), ew = expf(lw - mx);
    float sum = ex + ey + ez + ew;
#pragma unroll
    for (int o = 16; o; o >>= 1) sum += __shfl_xor_sync(0xffffffffu, sum, o);
    float inv = 1.0f / sum;
    float4 o4 = make_float4(ex * inv, ey * inv, ez * inv, ew * inv);
    *(float4*)(g_sim + ((size_t)b * 128 + c) * 128 + lane * 4) = o4;
}

// ---- k4: out[b] = M @ X, fp16 mma, A packed in-prologue from g_sim ----
// 144 CTAs = 8 b x 18 slices, 512 thr (16 warps 4x4, 32x32 warp tile).
#define ROWW 264
#define XBUF_WORDS (32 * ROWW)   // 8448

#define MMA_F16(d, a, bfr)                                             \
    asm volatile(                                                      \
        "mma.sync.aligned.m16n8k16.row.col.f32.f16.f16.f32 "           \
        "{%0,%1,%2,%3}, {%4,%5,%6,%7}, {%8,%9}, {%0,%1,%2,%3};"        \
        : "+f"(d[0]), "+f"(d[1]), "+f"(d[2]), "+f"(d[3])               \
        : "r"(a[0]), "r"(a[1]), "r"(a[2]), "r"(a[3]),                  \
          "r"(bfr[0]), "r"(bfr[1]))

__global__ __launch_bounds__(512, 1) void k4_gemm(const float* __restrict__ x,
                                                  float* __restrict__ out)
{
    extern __shared__ unsigned smu[];
    unsigned* Ms  = smu;                 // 8192 words (A fragment image)
    unsigned* Xb0 = smu + 8192;          // 2 x 8448 words

    int b     = blockIdx.x & 7;
    int slice = blockIdx.x >> 3;  // 0..17
    int tid   = threadIdx.x;

    // --- fused k3b: pack A fragments from g_sim (L2-hot, 64KB/CTA) ---
    {
        const float* sb = g_sim + (size_t)b * 16384;
        for (int i = 0; i < 16; i++) {
            int idx = tid + i * 512;
            int word = idx & 3, lane = (idx >> 2) & 31, cg = (idx >> 7) & 7, ks = idx >> 10;
            int lm = lane & 3, l4 = lane >> 2;
            int kh = ks * 8 + lm + ((word & 2) ? 4 : 0);
            int m  = cg * 16 + l4 + ((word & 1) ? 8 : 0);
            float s0 = sb[(2 * kh) * 128 + m];
            float s1 = sb[(2 * kh + 1) * 128 + m];
            unsigned wv;
            asm("cvt.rn.f16x2.f32 %0, %1, %2;" : "=r"(wv) : "f"(s1), "f"(s0));
            Ms[idx] = wv;
        }
    }

    const float* xb = x   + (size_t)b * 128 * 65536;
    float*       ob = out + (size_t)b * 128 * 65536;

    int khs  = tid >> 3;          // k-pair row 0..63
    int nseg = (tid & 7) << 4;    // staged c base
    int w    = tid >> 5;
    int lane = tid & 31;
    int wm = (w & 3) * 32, wn = (w >> 2) * 32;
    int l4 = lane >> 2, lm = lane & 3;

    int rr  = (khs >> 3) * 4 + (khs & 3);
    int hi  = (khs >> 2) & 1;
    unsigned sbase = (unsigned)(rr * ROWW + nseg * 2 + hi);

    const float* p0 = xb + (size_t)(2 * khs) * 65536 + nseg;
    const float* p1 = p0 + 65536;

    float4 r0[4], r1[4];
    {
        const float* q0 = p0 + (size_t)slice * 128;
        const float* q1 = p1 + (size_t)slice * 128;
#pragma unroll
        for (int j = 0; j < 4; j++) { r0[j] = *(const float4*)(q0 + 4 * j);
                                      r1[j] = *(const float4*)(q1 + 4 * j); }
    }

    int it = 0;
    for (int t = slice; t < 512; t += 18, it++) {
        unsigned* Xs = Xb0 + (it & 1) * XBUF_WORDS;
#pragma unroll
        for (int j = 0; j < 4; j++) {
            const float* e0 = (const float*)&r0[j];
            const float* e1 = (const float*)&r1[j];
#pragma unroll
            for (int e = 0; e < 4; e++) {
                unsigned wv;  // lo = h(x@k even), hi = h(x@k odd)
                asm("cvt.rn.f16x2.f32 %0, %1, %2;" : "=r"(wv) : "f"(e1[e]), "f"(e0[e]));
                Xs[sbase + (4 * j + e) * 2] = wv;
            }
        }
        __syncthreads();   // single barrier per iter (covers Ms on it==0)

        if (t + 18 < 512) {
            const float* q0 = p0 + (size_t)(t + 18) * 128;
            const float* q1 = p1 + (size_t)(t + 18) * 128;
#pragma unroll
            for (int j = 0; j < 4; j++) { r0[j] = *(const float4*)(q0 + 4 * j);
                                          r1[j] = *(const float4*)(q1 + 4 * j); }
        }

        float acc[2][4][4];
#pragma unroll
        for (int mi = 0; mi < 2; mi++)
#pragma unroll
            for (int ni = 0; ni < 4; ni++)
#pragma unroll
                for (int e = 0; e < 4; e++) acc[mi][ni][e] = 0.f;

#pragma unroll
        for (int ks = 0; ks < 8; ks++) {
            uint4 a0 = *(const uint4*)&Ms[ks * 1024 + ((w & 3) * 2 + 0) * 128 + lane * 4];
            uint4 a1 = *(const uint4*)&Ms[ks * 1024 + ((w & 3) * 2 + 1) * 128 + lane * 4];
            unsigned ah0[4] = {a0.x, a0.y, a0.z, a0.w};
            unsigned ah1[4] = {a1.x, a1.y, a1.z, a1.w};
            const unsigned* brow = Xs + (ks * 4 + lm) * ROWW;
            unsigned bh[4][2];
#pragma unroll
            for (int ni = 0; ni < 4; ni++) {
                uint2 bv = *(const uint2*)&brow[(wn + 8 * ni + l4) * 2];
                bh[ni][0] = bv.x; bh[ni][1] = bv.y;
            }
#pragma unroll
            for (int ni = 0; ni < 4; ni++) {
                MMA_F16(acc[0][ni], ah0, bh[ni]);
                MMA_F16(acc[1][ni], ah1, bh[ni]);
            }
        }

#pragma unroll
        for (int mi = 0; mi < 2; mi++) {
            int row = wm + 16 * mi + l4;
#pragma unroll
            for (int ni = 0; ni < 4; ni++) {
                int col = t * 128 + wn + 8 * ni + 2 * lm;
                float2 v0 = {acc[mi][ni][0], acc[mi][ni][1]};
                float2 v1 = {acc[mi][ni][2], acc[mi][ni][3]};
                *(float2*)(ob + (size_t)row * 65536 + col)       = v0;
                *(float2*)(ob + (size_t)(row + 8) * 65536 + col) = v1;
            }
        }
    }
}

// ---------------------------------------------------------------------------
extern "C" void kernel_launch(void* const* d_in, const int* in_sizes, int n_in,
                              void* d_out, int out_size)
{
    const float* x  = (const float*)d_in[0];
    const float* w1 = (const float*)d_in[1];
    const float* g1 = (const float*)d_in[2];
    const float* b1 = (const float*)d_in[3];
    const float* m1 = (const float*)d_in[4];
    const float* v1 = (const float*)d_in[5];
    const float* a1 = (const float*)d_in[6];
    const float* w2 = (const float*)d_in[7];
    const float* g2 = (const float*)d_in[8];
    const float* b2 = (const float*)d_in[9];
    const float* m2 = (const float*)d_in[10];
    const float* v2 = (const float*)d_in[11];
    const float* a2 = (const float*)d_in[12];
    float* out = (float*)d_out;

    const int SM1 = (XS_H * XS_W + 65 * P1_W) * 4;       // 86328
    const int SM2 = 128 * PS_STRIDE * 4;                 // 69632
    const int SM4 = (8192 + 2 * XBUF_WORDS) * 4;         // 100352
    static bool attr_done = false;
    if (!attr_done) {
        cudaFuncSetAttribute(k1_pool, cudaFuncAttributeMaxDynamicSharedMemorySize, SM1);
        cudaFuncSetAttribute(k2_gram, cudaFuncAttributeMaxDynamicSharedMemorySize, SM2);
        cudaFuncSetAttribute(k4_gemm, cudaFuncAttributeMaxDynamicSharedMemorySize, SM4);
        attr_done = true;
    }

    k1_pool<<<dim3(1024, 4), K1T, SM1>>>(x, w1, g1, b1, m1, v1, a1,
                                         w2, g2, b2, m2, v2, a2);
    k2_gram<<<256, 256, SM2>>>();
    k3_softmax<<<dim3(8, 16), 256>>>();
    k4_gemm<<<144, 512, SM4>>>(x, out);
}